// round 5
// baseline (speedup 1.0000x reference)
#include <cuda_runtime.h>
#include <math.h>

#define BB    16
#define TT    50
#define GG    64
#define NA    3
#define NC    80
#define CELLS (BB*NA*GG*GG)      // 196608
#define NTGT  (BB*TT)            // 800
#define PLANE 4096               // GG*GG
#define BMW   384                // bitmap words per batch (3*4096/32)
#define NBLK  256
#define DENSE_T 49152            // 48 conf planes * 1024 float4

// Anchors / 8 (grid units)
__constant__ float c_aw[9] = {1.25f, 2.0f, 4.125f, 3.75f, 7.75f, 7.375f, 14.5f, 19.5f, 46.625f};
__constant__ float c_ah[9] = {1.625f, 3.75f, 2.875f, 7.625f, 5.625f, 14.875f, 11.25f, 24.75f, 40.75f};

// Tiny global scratch. All of it is reset by the finalize block at the END of
// each call, so every graph replay starts from a clean state (first call uses
// static zero-init). No init kernel needed.
__device__ int          g_nwin, g_nclr, g_bcount;
__device__ volatile int g_ready;
__device__ int          g_win[NTGT * 6];   // {b<<14|cell, t, bits0, bits1, bits2, cleared}
__device__ int          g_clr[NTGT * 3];   // b<<14|cell
// g_acc: 0 bbox, 1 obj_num, 2 zcorr, 3 cls_num, 4 n_obj, 5 clr_sp, 6 dense_sp
__device__ float        g_acc[8];

__device__ __forceinline__ float softplusf(float z) { return __logf(1.0f + __expf(z)); }
__device__ __forceinline__ float sigmf(float z)     { return 1.0f / (1.0f + __expf(-z)); }

__global__ void __launch_bounds__(256) k_all(const float* __restrict__ bb,
                                             const float* __restrict__ gt,
                                             float* __restrict__ out) {
    __shared__ unsigned s_bm[BB * BMW];                  // 24 KB
    __shared__ int s_cell[NTGT], s_t[NTGT], s_cls[NTGT]; // 9.6 KB
    __shared__ int s_cnt[BB];

    const int bid = blockIdx.x, tid = threadIdx.x, lane = tid & 31;

    if (bid == 0) {
        // ---------------- PREP (bitmap + dedup'd winner list) ----------------
        if (tid < BB) s_cnt[tid] = 0;
        for (int i = tid; i < BB * BMW; i += 256) s_bm[i] = 0u;
        __syncthreads();

        // Phase 1: targets -> bitmap + per-batch hit list
        for (int g = tid; g < NTGT; g += 256) {
            int b = g / TT, t = g % TT;
            const float* r = gt + g * 5;
            float x = r[0], y = r[1], w = r[2], h = r[3], c = r[4];
            if (!((x + y + w + h + c) > 0.0f)) continue;

            float gx = x * GG, gy = y * GG, gw = w * GG, gh = h * GG;
            int gi = (int)gy, gj = (int)gx;
            if (gi < 0 || gi >= GG || gj < 0 || gj >= GG) continue;

            float best_iou = -1.0f; int best = 0; float iouL[3];
            #pragma unroll
            for (int a = 0; a < 9; a++) {
                float inter = fminf(gw, c_aw[a]) * fminf(gh, c_ah[a]);
                float uni   = gw * gh + c_aw[a] * c_ah[a] - inter;
                float iou   = inter / (uni + 1e-16f);
                if (a >= 6) iouL[a - 6] = iou;
                if (iou > best_iou) { best_iou = iou; best = a; }
            }
            #pragma unroll
            for (int a = 0; a < NA; a++) {
                if (iouL[a] > 0.5f) {
                    int cell = a * PLANE + gi * GG + gj;
                    atomicOr(&s_bm[b * BMW + (cell >> 5)], 1u << (cell & 31));
                }
            }
            if (best >= 6) {
                int cell = (best - 6) * PLANE + gi * GG + gj;
                int slot = atomicAdd(&s_cnt[b], 1);
                int e = b * TT + slot;
                s_cell[e] = cell; s_t[e] = t; s_cls[e] = (int)c;
            }
        }
        __syncthreads();

        // Phase 2: resolve winners (last-wins by t) + class-bit union + cleared flag
        for (int idx = tid; idx < NTGT; idx += 256) {
            int b = idx / TT, s = idx % TT;
            if (s >= s_cnt[b]) continue;
            int e = b * TT + s;
            int cell = s_cell[e], t = s_t[e];
            bool win = true;
            unsigned b0 = 0, b1 = 0, b2 = 0;
            int n = s_cnt[b];
            for (int j = 0; j < n; j++) {
                int e2 = b * TT + j;
                if (s_cell[e2] == cell) {
                    if (s_t[e2] > t) win = false;
                    int c = s_cls[e2];
                    if (c < 32)      b0 |= 1u << c;
                    else if (c < 64) b1 |= 1u << (c - 32);
                    else             b2 |= 1u << (c - 64);
                }
            }
            if (win) {
                int cl = (s_bm[b * BMW + (cell >> 5)] >> (cell & 31)) & 1;
                int wslot = atomicAdd(&g_nwin, 1);
                int* W = &g_win[wslot * 6];
                W[0] = (b << 14) | cell; W[1] = t;
                W[2] = (int)b0; W[3] = (int)b1; W[4] = (int)b2; W[5] = cl;
            }
        }

        // Phase 3: bitmap -> compact cleared list
        for (int wi = tid; wi < BB * BMW; wi += 256) {
            unsigned word = s_bm[wi];
            if (!word) continue;
            int b = wi / BMW, base = (wi % BMW) << 5;
            while (word) {
                int bit = __ffs(word) - 1; word &= word - 1;
                int slot = atomicAdd(&g_nclr, 1);
                g_clr[slot] = (b << 14) | (base + bit);
            }
        }

        // Publish: every writer fences its own writes, then one thread raises flag.
        __threadfence();
        __syncthreads();
        if (tid == 0) g_ready = 1;
    } else {
        // ---------------- DENSE: softplus reduce over all conf logits --------
        float local = 0.0f;
        int i = (bid - 1) * 256 + tid;
        if (i < DENSE_T) {
            int plane = i >> 10;
            int pos   = (i & 1023) << 2;
            int b = plane / NA, a = plane % NA;
            const float4 v = *(const float4*)(bb + ((size_t)b * 255 + a * 85 + 4) * PLANE + pos);
            local = softplusf(v.x) + softplusf(v.y) + softplusf(v.z) + softplusf(v.w);
        }
        #pragma unroll
        for (int off = 16; off > 0; off >>= 1)
            local += __shfl_down_sync(0xFFFFFFFFu, local, off);
        if (lane == 0 && local != 0.0f) atomicAdd(&g_acc[6], local);

        // ---------------- wait for prep ----------------
        if (tid == 0) { while (g_ready == 0) __nanosleep(64); }
        __syncthreads();
        __threadfence();

        if (bid <= 100) {
            // -------- winners: ONE WARP PER WINNER (all gathers in flight) ---
            int e = (bid - 1) * 8 + (tid >> 5);   // 0..799
            if (e < g_nwin) {
                const int* W = &g_win[e * 6];
                int bc = W[0]; int b = bc >> 14, cell = bc & 16383;
                int t = W[1];
                unsigned bits0 = (unsigned)W[2], bits1 = (unsigned)W[3], bits2 = (unsigned)W[4];
                int cleared = W[5];
                int a = cell >> 12, ij = cell & (PLANE - 1);
                const float* base = bb + ((size_t)b * 255 + a * 85) * PLANE + ij;

                float cls = 0.0f;
                #pragma unroll
                for (int k = 0; k < 3; k++) {
                    int c = lane + k * 32;
                    if (c < NC) {
                        float z = base[(5 + c) * PLANE];
                        unsigned bit = (c < 32) ? ((bits0 >> c) & 1u)
                                      : (c < 64) ? ((bits1 >> (c - 32)) & 1u)
                                                 : ((bits2 >> (c - 64)) & 1u);
                        cls += softplusf(z) - (float)bit * z;
                    }
                }
                #pragma unroll
                for (int off = 16; off > 0; off >>= 1)
                    cls += __shfl_down_sync(0xFFFFFFFFu, cls, off);

                if (lane == 0) {
                    float z0 = base[0], z1 = base[PLANE], z2 = base[2 * PLANE],
                          z3 = base[3 * PLANE], z4 = base[4 * PLANE];
                    const float* r = gt + (b * TT + t) * 5;
                    float gx = r[0] * GG, gy = r[1] * GG, gw = r[2] * GG, gh = r[3] * GG;
                    int gi = (int)gy, gj = (int)gx;
                    float best_iou = -1.0f; int best = 0;
                    #pragma unroll
                    for (int k = 0; k < 9; k++) {
                        float inter = fminf(gw, c_aw[k]) * fminf(gh, c_ah[k]);
                        float uni   = gw * gh + c_aw[k] * c_ah[k] - inter;
                        float iou   = inter / (uni + 1e-16f);
                        if (iou > best_iou) { best_iou = iou; best = k; }
                    }
                    float tx = gx - (float)gj, ty = gy - (float)gi;
                    float tw = __logf(gw / c_aw[best] + 1e-16f);
                    float th = __logf(gh / c_ah[best] + 1e-16f);
                    float sx = sigmf(z0), sy = sigmf(z1);
                    float bbox = (sx - tx) * (sx - tx) + (sy - ty) * (sy - ty)
                               + (z2 - tw) * (z2 - tw) + (z3 - th) * (z3 - th);
                    atomicAdd(&g_acc[0], bbox);
                    atomicAdd(&g_acc[1], softplusf(z4) - z4);  // obj numerator
                    if (!cleared) atomicAdd(&g_acc[2], z4);    // noobj z-correction
                    atomicAdd(&g_acc[3], cls);
                    atomicAdd(&g_acc[4], 1.0f);                // n_obj
                }
            }
        } else {
            // -------- cleared cells: subtract softplus at cleared conf positions
            float csum = 0.0f;
            int ci = (bid - 101) * 256 + tid;
            if (ci < g_nclr) {
                int bc = g_clr[ci]; int b = bc >> 14, cell = bc & 16383;
                int a = cell >> 12, ij = cell & (PLANE - 1);
                float z = bb[((size_t)b * 255 + a * 85 + 4) * PLANE + ij];
                csum = softplusf(z);
            }
            #pragma unroll
            for (int off = 16; off > 0; off >>= 1)
                csum += __shfl_down_sync(0xFFFFFFFFu, csum, off);
            if (lane == 0 && csum != 0.0f) atomicAdd(&g_acc[5], csum);
        }
    }

    // ---------------- finalize: last block out; also resets state ------------
    __syncthreads();
    if (tid == 0) {
        __threadfence();
        int old = atomicAdd(&g_bcount, 1);
        if (old == NBLK - 1) {
            float n_obj   = fmaxf(g_acc[4], 1.0f);
            float n_noobj = fmaxf((float)CELLS - (float)g_nclr, 1.0f);
            float noobj_num = g_acc[6] - g_acc[5] - g_acc[2];
            float bbox = 5.0f * g_acc[0] / n_obj;
            float obj  = g_acc[1] / n_obj + 0.5f * noobj_num / n_noobj;
            float cls  = g_acc[3] / (n_obj * (float)NC);
            out[0] = bbox + obj + cls;
            out[1] = bbox;
            out[2] = obj;
            out[3] = cls;
            // Reset everything for the next graph replay
            #pragma unroll
            for (int k = 0; k < 8; k++) g_acc[k] = 0.0f;
            g_nwin = 0; g_nclr = 0; g_bcount = 0;
            __threadfence();
            g_ready = 0;
        }
    }
}

// ---------------------------------------------------------------------------
extern "C" void kernel_launch(void* const* d_in, const int* in_sizes, int n_in,
                              void* d_out, int out_size) {
    const float* backbone = (const float*)d_in[0];  // [16, 255, 64, 64] f32
    const float* gt       = (const float*)d_in[1];  // [16, 50, 5] f32
    float* out            = (float*)d_out;          // 4 f32

    k_all<<<NBLK, 256>>>(backbone, gt, out);
}

// round 7
// speedup vs baseline: 1.8054x; 1.8054x over previous
#include <cuda_runtime.h>
#include <math.h>

#define BB    16
#define TT    50
#define GG    64
#define NA    3
#define NC    80
#define CELLS (BB*NA*GG*GG)      // 196608
#define NTGT  (BB*TT)            // 800
#define PLANE 4096               // GG*GG
#define BMW   384                // bitmap words per batch (3*4096/32)
#define NBLK  256
#define NWARPS (NBLK*8)          // 2048
#define DENSE_T 49152            // 48 conf planes * 1024 float4
#define CLR_WARPS 96             // top warps handle cleared cells (<=2400)

// Anchors / 8 (grid units)
__constant__ float c_aw[9] = {1.25f, 2.0f, 4.125f, 3.75f, 7.75f, 7.375f, 14.5f, 19.5f, 46.625f};
__constant__ float c_ah[9] = {1.625f, 3.75f, 2.875f, 7.625f, 5.625f, 14.875f, 11.25f, 24.75f, 40.75f};

// Tiny global scratch; finalize block resets everything at end of each call
// (first call relies on static zero-init), so graph replays are clean.
__device__ int          g_nwin, g_nclr, g_bcount;
__device__ volatile int g_readyc;
__device__ int          g_win[NTGT * 6];   // {b<<14|cell, t, bits0, bits1, bits2, cleared}
__device__ int          g_clr[NTGT * 3];   // b<<14|cell
// g_acc: 0 bbox, 1 obj_num, 2 zcorr, 3 cls_num, 4 n_obj, 5 clr_sp, 6 dense_sp
__device__ float        g_acc[8];

__device__ __forceinline__ float softplusf(float z) { return __logf(1.0f + __expf(z)); }
__device__ __forceinline__ float sigmf(float z)     { return 1.0f / (1.0f + __expf(-z)); }

__global__ void __launch_bounds__(256) k_all(const float* __restrict__ bb,
                                             const float* __restrict__ gt,
                                             float* __restrict__ out) {
    __shared__ unsigned s_bm[BMW];                 // per-batch bitmap (prep blocks only)
    __shared__ int s_cell[TT], s_t[TT], s_cls[TT];
    __shared__ int s_cnt;

    const int bid = blockIdx.x, tid = threadIdx.x, lane = tid & 31;
    const int gw = bid * 8 + (tid >> 5);           // global warp id 0..2047

    if (bid < BB) {
        // ================= PREP: one block per batch =================
        const int b = bid;
        if (tid == 0) s_cnt = 0;
        for (int i = tid; i < BMW; i += 256) s_bm[i] = 0u;
        __syncthreads();

        if (tid < TT) {
            int t = tid;
            const float* r = gt + (b * TT + t) * 5;
            float x = r[0], y = r[1], w = r[2], h = r[3], c = r[4];
            if ((x + y + w + h + c) > 0.0f) {
                float gx = x * GG, gy = y * GG, gw_ = w * GG, gh = h * GG;
                int gi = (int)gy, gj = (int)gx;
                if (gi >= 0 && gi < GG && gj >= 0 && gj < GG) {
                    float best_iou = -1.0f; int best = 0; float iouL[3];
                    #pragma unroll
                    for (int a = 0; a < 9; a++) {
                        float inter = fminf(gw_, c_aw[a]) * fminf(gh, c_ah[a]);
                        float uni   = gw_ * gh + c_aw[a] * c_ah[a] - inter;
                        float iou   = inter / (uni + 1e-16f);
                        if (a >= 6) iouL[a - 6] = iou;
                        if (iou > best_iou) { best_iou = iou; best = a; }
                    }
                    #pragma unroll
                    for (int a = 0; a < NA; a++) {
                        if (iouL[a] > 0.5f) {
                            int cell = a * PLANE + gi * GG + gj;
                            atomicOr(&s_bm[cell >> 5], 1u << (cell & 31));
                        }
                    }
                    if (best >= 6) {
                        int cell = (best - 6) * PLANE + gi * GG + gj;
                        int slot = atomicAdd(&s_cnt, 1);
                        s_cell[slot] = cell; s_t[slot] = t; s_cls[slot] = (int)c;
                    }
                }
            }
        }
        __syncthreads();

        // resolve winners (last-wins by t) + class union + cleared flag
        int n = s_cnt;
        if (tid < n) {
            int cell = s_cell[tid], t = s_t[tid];
            bool win = true;
            unsigned b0 = 0, b1 = 0, b2 = 0;
            for (int j = 0; j < n; j++) {
                if (s_cell[j] == cell) {
                    if (s_t[j] > t) win = false;
                    int c = s_cls[j];
                    if (c < 32)      b0 |= 1u << c;
                    else if (c < 64) b1 |= 1u << (c - 32);
                    else             b2 |= 1u << (c - 64);
                }
            }
            if (win) {
                int cl = (s_bm[cell >> 5] >> (cell & 31)) & 1;
                int wslot = atomicAdd(&g_nwin, 1);
                int* W = &g_win[wslot * 6];
                W[0] = (b << 14) | cell; W[1] = t;
                W[2] = (int)b0; W[3] = (int)b1; W[4] = (int)b2; W[5] = cl;
            }
        }

        // bitmap -> compact cleared list
        for (int wi = tid; wi < BMW; wi += 256) {
            unsigned word = s_bm[wi];
            if (!word) continue;
            int base = wi << 5;
            while (word) {
                int bit = __ffs(word) - 1; word &= word - 1;
                int slot = atomicAdd(&g_nclr, 1);
                g_clr[slot] = (b << 14) | (base + bit);
            }
        }
        __threadfence();
        __syncthreads();
        if (tid == 0) atomicAdd((int*)&g_readyc, 1);
    } else {
        // ============ DENSE: softplus reduce over all conf logits ============
        float local = 0.0f;
        int i = (bid - BB) * 256 + tid;
        if (i < DENSE_T) {
            int plane = i >> 10;
            int pos   = (i & 1023) << 2;
            int b = plane / NA, a = plane % NA;
            const float4 v = *(const float4*)(bb + ((size_t)b * 255 + a * 85 + 4) * PLANE + pos);
            local = softplusf(v.x) + softplusf(v.y) + softplusf(v.z) + softplusf(v.w);
        }
        #pragma unroll
        for (int off = 16; off > 0; off >>= 1)
            local += __shfl_down_sync(0xFFFFFFFFu, local, off);
        if (lane == 0 && local != 0.0f) atomicAdd(&g_acc[6], local);
    }

    // ================= wait for all 16 prep blocks =================
    if (tid == 0) { while (g_readyc < BB) __nanosleep(32); }
    __syncthreads();
    __threadfence();

    const int nwin = g_nwin;
    const int nclr = g_nclr;

    if (gw < nwin) {
        // ============ WINNERS: one warp per winner, 4 batched LDGs ===========
        const int* W = &g_win[gw * 6];
        int bc = W[0]; int b = bc >> 14, cell = bc & 16383;
        int t = W[1];
        unsigned bits0 = (unsigned)W[2], bits1 = (unsigned)W[3], bits2 = (unsigned)W[4];
        int cleared = W[5];
        int a = cell >> 12, ij = cell & (PLANE - 1);
        const float* base = bb + ((size_t)b * 255 + a * 85) * PLANE + ij;

        // batch all loads: head attrs (lanes 0..4) + 80 class planes
        float zh  = (lane < 5)  ? base[lane * PLANE]        : 0.0f;
        float za  = base[(5 + lane) * PLANE];
        float zb  = base[(37 + lane) * PLANE];
        float zc  = (lane < 16) ? base[(69 + lane) * PLANE] : 0.0f;

        float cls = 0.0f;
        {
            unsigned bitA = (bits0 >> lane) & 1u;
            unsigned bitB = (bits1 >> lane) & 1u;
            cls += softplusf(za) - (float)bitA * za;
            cls += softplusf(zb) - (float)bitB * zb;
            if (lane < 16) {
                unsigned bitC = (bits2 >> lane) & 1u;
                cls += softplusf(zc) - (float)bitC * zc;
            }
        }
        #pragma unroll
        for (int off = 16; off > 0; off >>= 1)
            cls += __shfl_down_sync(0xFFFFFFFFu, cls, off);

        float z0 = __shfl_sync(0xFFFFFFFFu, zh, 0);
        float z1 = __shfl_sync(0xFFFFFFFFu, zh, 1);
        float z2 = __shfl_sync(0xFFFFFFFFu, zh, 2);
        float z3 = __shfl_sync(0xFFFFFFFFu, zh, 3);
        float z4 = __shfl_sync(0xFFFFFFFFu, zh, 4);

        if (lane == 0) {
            const float* r = gt + (b * TT + t) * 5;
            float gx = r[0] * GG, gy = r[1] * GG, gw_ = r[2] * GG, gh = r[3] * GG;
            int gi = (int)gy, gj = (int)gx;
            float best_iou = -1.0f; int best = 0;
            #pragma unroll
            for (int k = 0; k < 9; k++) {
                float inter = fminf(gw_, c_aw[k]) * fminf(gh, c_ah[k]);
                float uni   = gw_ * gh + c_aw[k] * c_ah[k] - inter;
                float iou   = inter / (uni + 1e-16f);
                if (iou > best_iou) { best_iou = iou; best = k; }
            }
            float tx = gx - (float)gj, ty = gy - (float)gi;
            float tw = __logf(gw_ / c_aw[best] + 1e-16f);
            float th = __logf(gh / c_ah[best] + 1e-16f);
            float sx = sigmf(z0), sy = sigmf(z1);
            float bbox = (sx - tx) * (sx - tx) + (sy - ty) * (sy - ty)
                       + (z2 - tw) * (z2 - tw) + (z3 - th) * (z3 - th);
            atomicAdd(&g_acc[0], bbox);
            atomicAdd(&g_acc[1], softplusf(z4) - z4);   // obj numerator
            if (!cleared) atomicAdd(&g_acc[2], z4);     // noobj z-correction
            atomicAdd(&g_acc[3], cls);
            atomicAdd(&g_acc[4], 1.0f);                 // n_obj
        }
    } else if (gw >= NWARPS - CLR_WARPS) {
        // ============ CLEARED: subtract softplus at cleared conf cells =======
        int ci = (gw - (NWARPS - CLR_WARPS)) * 32 + lane;
        float csum = 0.0f;
        if (ci < nclr) {
            int bc = g_clr[ci]; int b = bc >> 14, cell = bc & 16383;
            int a = cell >> 12, ij = cell & (PLANE - 1);
            float z = bb[((size_t)b * 255 + a * 85 + 4) * PLANE + ij];
            csum = softplusf(z);
        }
        #pragma unroll
        for (int off = 16; off > 0; off >>= 1)
            csum += __shfl_down_sync(0xFFFFFFFFu, csum, off);
        if (lane == 0 && csum != 0.0f) atomicAdd(&g_acc[5], csum);
    }

    // ================= finalize: last block out; reset state =================
    __syncthreads();
    if (tid == 0) {
        __threadfence();
        int old = atomicAdd(&g_bcount, 1);
        if (old == NBLK - 1) {
            float n_obj   = fmaxf(g_acc[4], 1.0f);
            float n_noobj = fmaxf((float)CELLS - (float)nclr, 1.0f);
            float noobj_num = g_acc[6] - g_acc[5] - g_acc[2];
            float bbox = 5.0f * g_acc[0] / n_obj;
            float obj  = g_acc[1] / n_obj + 0.5f * noobj_num / n_noobj;
            float cls  = g_acc[3] / (n_obj * (float)NC);
            out[0] = bbox + obj + cls;
            out[1] = bbox;
            out[2] = obj;
            out[3] = cls;
            #pragma unroll
            for (int k = 0; k < 8; k++) g_acc[k] = 0.0f;
            g_nwin = 0; g_nclr = 0; g_bcount = 0;
            __threadfence();
            g_readyc = 0;
        }
    }
}

// ---------------------------------------------------------------------------
extern "C" void kernel_launch(void* const* d_in, const int* in_sizes, int n_in,
                              void* d_out, int out_size) {
    const float* backbone = (const float*)d_in[0];  // [16, 255, 64, 64] f32
    const float* gt       = (const float*)d_in[1];  // [16, 50, 5] f32
    float* out            = (float*)d_out;          // 4 f32

    k_all<<<NBLK, 256>>>(backbone, gt, out);
}

// round 8
// speedup vs baseline: 3.5625x; 1.9732x over previous
#include <cuda_runtime.h>
#include <math.h>

#define BB    16
#define TT    50
#define GG    64
#define NA    3
#define NC    80
#define CELLS (BB*NA*GG*GG)      // 196608
#define NTGT  (BB*TT)            // 800
#define PLANE 4096               // GG*GG
#define NBLK  192                // 192*256 = 49152 threads = exactly the dense float4 count
#define FULL  0xFFFFFFFFu

// Anchors / 8 (grid units)
__constant__ float c_aw[9] = {1.25f, 2.0f, 4.125f, 3.75f, 7.75f, 7.375f, 14.5f, 19.5f, 46.625f};
__constant__ float c_ah[9] = {1.625f, 3.75f, 2.875f, 7.625f, 5.625f, 14.875f, 11.25f, 24.75f, 40.75f};

// g_acc: 0 bbox, 1 obj_num, 2 zcorr, 3 cls_num, 4 n_obj, 5 clr_sp, 6 n_clr, 7 dense_sp
// Reset by the finalize block at the end of every call (first call: static zero-init),
// so graph replays always start clean.
__device__ float g_acc[8];
__device__ int   g_bcount;

__device__ __forceinline__ float softplusf(float z) { return __logf(1.0f + __expf(z)); }
__device__ __forceinline__ float sigmf(float z)     { return 1.0f / (1.0f + __expf(-z)); }

__global__ void __launch_bounds__(256) k_all(const float* __restrict__ bb,
                                             const float* __restrict__ gt,
                                             float* __restrict__ out) {
    __shared__ float s_red[8];

    const int bid = blockIdx.x, tid = threadIdx.x, lane = tid & 31;
    const int gw = bid * 8 + (tid >> 5);   // global warp id

    if (tid < 8) s_red[tid] = 0.0f;
    __syncthreads();

    // ---------------- DENSE: one float4 softplus per thread (exact cover) ----
    float dsum;
    {
        int i = bid * 256 + tid;               // [0, 49152)
        int plane = i >> 10;                   // [0, 48)
        int pos   = (i & 1023) << 2;
        int b = plane / NA, a = plane % NA;
        const float4 v = *(const float4*)(bb + ((size_t)b * 255 + a * 85 + 4) * PLANE + pos);
        dsum = softplusf(v.x) + softplusf(v.y) + softplusf(v.z) + softplusf(v.w);
    }
    #pragma unroll
    for (int off = 16; off > 0; off >>= 1)
        dsum += __shfl_down_sync(FULL, dsum, off);
    if (lane == 0) atomicAdd(&s_red[7], dsum);

    // ---------------- TARGET WARPS: warp (b,t0) resolves itself locally ------
    if (gw < NTGT) {
        const int b  = gw / TT;
        const int t0 = gw % TT;
        const float* gtb = gt + b * TT * 5;

        // per-lane slots: targets lane and 32+lane
        int   pos_[2]  = {-1, -1};   // gi*64+gj, -1 if invalid
        int   cell_[2] = {-1, -1};   // full cell if hit (best local), else -1
        int   clr_[2]  = {0, 0};     // 3 bits: local anchor IOU > 0.5
        int   cls_[2]  = {0, 0};
        int   best_[2] = {0, 0};
        float GX[2], GY[2], GW_[2], GH[2];

        #pragma unroll
        for (int j = 0; j < 2; j++) {
            int tj = lane + 32 * j;
            if (tj < TT) {
                const float* r = gtb + tj * 5;
                float x = r[0], y = r[1], w = r[2], h = r[3], c = r[4];
                if ((x + y + w + h + c) > 0.0f) {
                    float gx = x * GG, gy = y * GG, gwf = w * GG, ghf = h * GG;
                    int gi = (int)gy, gj = (int)gx;
                    if (gi >= 0 && gi < GG && gj >= 0 && gj < GG) {
                        pos_[j] = gi * GG + gj;
                        float bi = -1.0f; int bst = 0;
                        #pragma unroll
                        for (int a = 0; a < 9; a++) {
                            float inter = fminf(gwf, c_aw[a]) * fminf(ghf, c_ah[a]);
                            float uni   = gwf * ghf + c_aw[a] * c_ah[a] - inter;
                            float iou   = inter / (uni + 1e-16f);
                            if (a >= 6 && iou > 0.5f) clr_[j] |= 1 << (a - 6);
                            if (iou > bi) { bi = iou; bst = a; }
                        }
                        best_[j] = bst;
                        if (bst >= 6) cell_[j] = (bst - 6) * PLANE + pos_[j];
                        cls_[j] = (int)c;
                        GX[j] = gx; GY[j] = gy; GW_[j] = gwf; GH[j] = ghf;
                    }
                }
            }
        }

        const int srcl = t0 & 31, srcs = t0 >> 5;
        // broadcast t0's pos / cell / clr bits to the whole warp
        int p0 = __shfl_sync(FULL, pos_[0],  srcl), p1 = __shfl_sync(FULL, pos_[1],  srcl);
        int c0 = __shfl_sync(FULL, cell_[0], srcl), c1 = __shfl_sync(FULL, cell_[1], srcl);
        int r0 = __shfl_sync(FULL, clr_[0],  srcl), r1 = __shfl_sync(FULL, clr_[1],  srcl);
        const int pos_t0  = srcs ? p1 : p0;
        const int cell_t0 = srcs ? c1 : c0;
        const int clr_t0  = srcs ? r1 : r0;

        // ---- cleared-cell ownership per local anchor (owner = min t) ----
        int owned[3], cellcleared[3];
        #pragma unroll
        for (int a = 0; a < 3; a++) {
            unsigned m0 = __ballot_sync(FULL, ((clr_[0] >> a) & 1) && (pos_[0] == pos_t0));
            unsigned m1 = __ballot_sync(FULL, ((clr_[1] >> a) & 1) && (pos_[1] == pos_t0));
            cellcleared[a] = (m0 | m1) != 0u;
            int omin = m0 ? (__ffs(m0) - 1) : (m1 ? (32 + __ffs(m1) - 1) : 64);
            owned[a] = ((clr_t0 >> a) & 1) && (omin == t0);
        }
        // lane a (<3) accumulates the owned cleared-cell corrections
        if (lane < 3 && owned[lane]) {
            float z = bb[((size_t)b * 255 + lane * 85 + 4) * PLANE + pos_t0];
            atomicAdd(&s_red[5], softplusf(z));
            atomicAdd(&s_red[6], 1.0f);
        }

        // ---- winner resolution (last-wins by t at the same cell) ----
        unsigned w0 = __ballot_sync(FULL, (cell_[0] >= 0) && (cell_[0] == cell_t0));
        unsigned w1 = __ballot_sync(FULL, (cell_[1] >= 0) && (cell_[1] == cell_t0));
        int mx = w1 ? (32 + 31 - __clz(w1)) : (w0 ? (31 - __clz(w0)) : -1);
        const bool winner = (cell_t0 >= 0) && (mx == t0);

        // class-bit union over all hits at this cell (order-independent)
        unsigned cb0 = 0, cb1 = 0, cb2 = 0;
        #pragma unroll
        for (int j = 0; j < 2; j++) {
            if (cell_[j] >= 0 && cell_[j] == cell_t0) {
                int c = cls_[j];
                if (c < 32)      cb0 |= 1u << c;
                else if (c < 64) cb1 |= 1u << (c - 32);
                else             cb2 |= 1u << (c - 64);
            }
        }
        #pragma unroll
        for (int off = 16; off > 0; off >>= 1) {
            cb0 |= __shfl_xor_sync(FULL, cb0, off);
            cb1 |= __shfl_xor_sync(FULL, cb1, off);
            cb2 |= __shfl_xor_sync(FULL, cb2, off);
        }

        if (winner) {
            const int a_win = cell_t0 >> 12;
            const int ij    = cell_t0 & (PLANE - 1);
            const bool cleared = cellcleared[a_win] != 0;
            const float* base = bb + ((size_t)b * 255 + a_win * 85) * PLANE + ij;

            // batched gather: head attrs (lanes 0..4) + 80 class planes
            float zh = (lane < 5)  ? base[lane * PLANE]        : 0.0f;
            float za = base[(5 + lane) * PLANE];
            float zb = base[(37 + lane) * PLANE];
            float zc = (lane < 16) ? base[(69 + lane) * PLANE] : 0.0f;

            float cls = softplusf(za) - (float)((cb0 >> lane) & 1u) * za
                      + softplusf(zb) - (float)((cb1 >> lane) & 1u) * zb;
            if (lane < 16) cls += softplusf(zc) - (float)((cb2 >> lane) & 1u) * zc;
            #pragma unroll
            for (int off = 16; off > 0; off >>= 1)
                cls += __shfl_down_sync(FULL, cls, off);

            float z0 = __shfl_sync(FULL, zh, 0);
            float z1 = __shfl_sync(FULL, zh, 1);
            float z2 = __shfl_sync(FULL, zh, 2);
            float z3 = __shfl_sync(FULL, zh, 3);
            float z4 = __shfl_sync(FULL, zh, 4);

            if (lane == srcl) {
                float gx = srcs ? GX[1] : GX[0];
                float gy = srcs ? GY[1] : GY[0];
                float gwf = srcs ? GW_[1] : GW_[0];
                float ghf = srcs ? GH[1] : GH[0];
                int best  = srcs ? best_[1] : best_[0];
                int gi = (int)gy, gj = (int)gx;
                float tx = gx - (float)gj, ty = gy - (float)gi;
                float tw = __logf(gwf / c_aw[best] + 1e-16f);
                float th = __logf(ghf / c_ah[best] + 1e-16f);
                float sx = sigmf(z0), sy = sigmf(z1);
                float bbox = (sx - tx) * (sx - tx) + (sy - ty) * (sy - ty)
                           + (z2 - tw) * (z2 - tw) + (z3 - th) * (z3 - th);
                atomicAdd(&s_red[0], bbox);
                atomicAdd(&s_red[1], softplusf(z4) - z4);   // obj numerator
                if (!cleared) atomicAdd(&s_red[2], z4);     // noobj z-correction
                atomicAdd(&s_red[4], 1.0f);                 // n_obj
            }
            if (lane == 0) atomicAdd(&s_red[3], cls);
        }
    }

    // ---------------- block -> global accumulate, then finalize --------------
    __syncthreads();
    if (tid < 8) {
        float v = s_red[tid];
        if (v != 0.0f) atomicAdd(&g_acc[tid], v);
        __threadfence();
    }
    __syncthreads();
    if (tid == 0) {
        int old = atomicAdd(&g_bcount, 1);
        if (old == NBLK - 1) {
            __threadfence();
            float n_obj   = fmaxf(g_acc[4], 1.0f);
            float n_noobj = fmaxf((float)CELLS - g_acc[6], 1.0f);
            float noobj_num = g_acc[7] - g_acc[5] - g_acc[2];
            float bbox = 5.0f * g_acc[0] / n_obj;
            float obj  = g_acc[1] / n_obj + 0.5f * noobj_num / n_noobj;
            float cls  = g_acc[3] / (n_obj * (float)NC);
            out[0] = bbox + obj + cls;
            out[1] = bbox;
            out[2] = obj;
            out[3] = cls;
            #pragma unroll
            for (int k = 0; k < 8; k++) g_acc[k] = 0.0f;
            g_bcount = 0;
        }
    }
}

// ---------------------------------------------------------------------------
extern "C" void kernel_launch(void* const* d_in, const int* in_sizes, int n_in,
                              void* d_out, int out_size) {
    const float* backbone = (const float*)d_in[0];  // [16, 255, 64, 64] f32
    const float* gt       = (const float*)d_in[1];  // [16, 50, 5] f32
    float* out            = (float*)d_out;          // 4 f32

    k_all<<<NBLK, 256>>>(backbone, gt, out);
}